// round 7
// baseline (speedup 1.0000x reference)
#include <cuda_runtime.h>
#include <cuda_bf16.h>
#include <cuda_fp8.h>
#include <cstdint>

// Problem shape (fixed by the dataset): M=8192 (B*T), K=4096 (C), N=16384 (O)
#define MAX_M 8192
#define MAX_K 4096
#define MAX_N 16384

// FP8 scratch (device globals: no allocation allowed in kernel_launch)
__device__ __align__(128) uint8_t g_Xq[(size_t)MAX_M * MAX_K];  // 32 MB
__device__ __align__(128) uint8_t g_Wq[(size_t)MAX_N * MAX_K];  // 64 MB

// ----------------------------- helpers -------------------------------------
__device__ __forceinline__ uint32_t smem_u32(const void* p) {
    uint32_t a;
    asm("{ .reg .u64 t; cvta.to.shared.u64 t, %1; cvt.u32.u64 %0, t; }"
        : "=r"(a) : "l"(p));
    return a;
}

#define CP_ASYNC16(saddr, gptr) \
    asm volatile("cp.async.cg.shared.global [%0], [%1], 16;" :: "r"(saddr), "l"(gptr))
#define CP_COMMIT() asm volatile("cp.async.commit_group;" ::: "memory")
#define CP_WAIT(n)  asm volatile("cp.async.wait_group %0;" :: "n"(n) : "memory")

__device__ __forceinline__ void ldsm_x4(uint32_t* r, uint32_t addr) {
    asm volatile("ldmatrix.sync.aligned.m8n8.x4.shared.b16 {%0,%1,%2,%3}, [%4];"
                 : "=r"(r[0]), "=r"(r[1]), "=r"(r[2]), "=r"(r[3]) : "r"(addr));
}

// FP8 e4m3 x e4m3 -> f32 MMA (sm_89+, family-portable)
__device__ __forceinline__ void mma_f8(float* c, const uint32_t* a, const uint32_t* b) {
    asm volatile(
        "mma.sync.aligned.m16n8k32.row.col.f32.e4m3.e4m3.f32 "
        "{%0,%1,%2,%3}, {%4,%5,%6,%7}, {%8,%9}, {%0,%1,%2,%3};"
        : "+f"(c[0]), "+f"(c[1]), "+f"(c[2]), "+f"(c[3])
        : "r"(a[0]), "r"(a[1]), "r"(a[2]), "r"(a[3]), "r"(b[0]), "r"(b[1]));
}

// ------------------------------ constants -----------------------------------
#define BM 256
#define BN 128
#define BK 128
#define STAGES 4
#define STAGE_A (BM * BK)                       // 32768
#define STAGE_B (BN * BK)                       // 16384
#define STAGE_BYTES (STAGE_A + STAGE_B)         // 49152
#define SMEM_TOTAL (STAGES * STAGE_BYTES)       // 196608

// ------------------------------ quantize ------------------------------------
// Fused single launch (keeps ncu's -s 5 -c 1 window on the GEMM).
// satfinite e4m3 == clamp(-448,448) + round-to-nearest-even -> matches reference
__device__ __forceinline__ uint32_t q4(const float4 v) {
    __nv_fp8x2_storage_t lo =
        __nv_cvt_float2_to_fp8x2(make_float2(v.x, v.y), __NV_SATFINITE, __NV_E4M3);
    __nv_fp8x2_storage_t hi =
        __nv_cvt_float2_to_fp8x2(make_float2(v.z, v.w), __NV_SATFINITE, __NV_E4M3);
    return (uint32_t)lo | ((uint32_t)hi << 16);
}

__global__ void quant_fp8_fused_kernel(const float* __restrict__ x,
                                       const float* __restrict__ w,
                                       uint32_t* __restrict__ xq,
                                       uint32_t* __restrict__ wq,
                                       int n4x, int n4w) {
    int i = blockIdx.x * blockDim.x + threadIdx.x;
    if (i < n4x) {
        xq[i] = q4(((const float4*)x)[i]);
    } else {
        int j = i - n4x;
        if (j < n4w) wq[j] = q4(((const float4*)w)[j]);
    }
}

// ------------------------------- GEMM ----------------------------------------
// 8 warps (256 threads), warp tile 64x64: 4 M-warps x 2 N-warps.
// 1 CTA/SM -> 256 regs/thread. Fragments double-buffered across ks-steps so
// every LDSM batch is issued one full MMA-burst (512 tensor-cyc) early.
__global__ void __launch_bounds__(256, 1)
fp8_gemm_kernel(const float* __restrict__ bias, float* __restrict__ out,
                int M, int N, int K) {
    extern __shared__ char smem[];
    const uint32_t sbase = smem_u32(smem);
    const int tid  = threadIdx.x;
    const int wid  = tid >> 5;
    const int lane = tid & 31;
    const int wm = wid & 3;    // 4 M-warps x 64 rows
    const int wn = wid >> 2;   // 2 N-warps x 64 cols

    // ---- grouped rasterization for L2 reuse ----
    const int tiles_m = M / BM;   // 32
    const int tiles_n = N / BN;   // 128
    const int GRP = 8;
    int bid = blockIdx.x;
    int tpg = GRP * tiles_n;
    int g = bid / tpg, r = bid % tpg;
    int mf = g * GRP;
    int gs = tiles_m - mf; if (gs > GRP) gs = GRP;
    const int m0 = (mf + (r % gs)) * BM;
    const int n0 = (r / gs) * BN;

    const uint8_t* Ag = g_Xq + (size_t)m0 * K;
    const uint8_t* Bg = g_Wq + (size_t)n0 * K;

    // loader: per chunk 3072 x 16B units (A 2048 + B 1024); 12 per thread.
    // rows are 128B; swizzle unit column: cu = c ^ (row & 7) -> conflict-free.
    auto load_chunk = [&](int ck, int buf) {
        const uint32_t st = sbase + buf * STAGE_BYTES;
#pragma unroll
        for (int j = 0; j < 12; j++) {
            int u = tid + 256 * j;
            if (u < 2048) {
                int row = u >> 3, c = u & 7;
                CP_ASYNC16(st + row * 128 + ((c ^ (row & 7)) << 4),
                           Ag + (size_t)row * K + ck * BK + c * 16);
            } else {
                int v = u - 2048;
                int row = v >> 3, c = v & 7;
                CP_ASYNC16(st + STAGE_A + row * 128 + ((c ^ (row & 7)) << 4),
                           Bg + (size_t)row * K + ck * BK + c * 16);
            }
        }
    };

    float acc[4][8][4];
#pragma unroll
    for (int mi = 0; mi < 4; mi++)
#pragma unroll
        for (int ni = 0; ni < 8; ni++)
#pragma unroll
            for (int q = 0; q < 4; q++) acc[mi][ni][q] = 0.f;

    const int NC = K / BK;   // 32

    // lane-derived ldmatrix address components (mapping verified rel_err=0)
    const int lr   = lane & 7;
    const int lsel = lane >> 3;                 // 0..3
    const int a_row_off = lr + (lsel & 1) * 8;  // A: bit0 -> +8 rows
    const int a_ku      = lsel >> 1;            //    bit1 -> k-unit
    const int b_ni_off  = lsel >> 1;            // B: bit1 -> n8 within pair
    const int b_ku      = lsel & 1;             //    bit0 -> k-unit

    // fragment double-buffer
    uint32_t afr[2][4][4];
    uint32_t bfr[2][8][2];

    // load all fragments of ks-step `ks` from buffer `buf` into parity `pb`
    auto ldfrag = [&](int buf, int ks, int pb) {
        const uint32_t sA = sbase + buf * STAGE_BYTES;
        const uint32_t sB = sA + STAGE_A;
#pragma unroll
        for (int mi = 0; mi < 4; mi++) {
            int row  = wm * 64 + mi * 16 + a_row_off;
            int unit = ks * 2 + a_ku;
            ldsm_x4(afr[pb][mi], sA + row * 128 + ((unit ^ (row & 7)) << 4));
        }
#pragma unroll
        for (int nj = 0; nj < 4; nj++) {
            int nrow = wn * 64 + (nj * 2 + b_ni_off) * 8 + lr;
            int unit = ks * 2 + b_ku;
            uint32_t t[4];
            ldsm_x4(t, sB + nrow * 128 + ((unit ^ (nrow & 7)) << 4));
            bfr[pb][nj * 2 + 0][0] = t[0]; bfr[pb][nj * 2 + 0][1] = t[1];
            bfr[pb][nj * 2 + 1][0] = t[2]; bfr[pb][nj * 2 + 1][1] = t[3];
        }
    };

    auto domma = [&](int pb) {
#pragma unroll
        for (int mi = 0; mi < 4; mi++)
#pragma unroll
            for (int ni = 0; ni < 8; ni++)
                mma_f8(acc[mi][ni], afr[pb][mi], bfr[pb][ni]);
    };

    // ---- pipeline: 2-chunk window per barrier; fragments flow continuously --
    load_chunk(0, 0); CP_COMMIT();
    load_chunk(1, 1); CP_COMMIT();

    for (int i = 0; i < NC; i += 2) {
        CP_WAIT(0);          // chunks i, i+1 resident (issued 1 iteration ago)
        __syncthreads();     // bufs (i+2)%4,(i+3)%4 free; smem data visible
        if (i + 2 < NC) load_chunk(i + 2, (i + 2) & 3);
        CP_COMMIT();

        const int buf0 = i & 3, buf1 = (i + 1) & 3;
        ldfrag(buf0, 0, 0);                       // prime the fragment pipe
#pragma unroll
        for (int s = 0; s < 8; s++) {             // 8 ks-steps over 2 chunks
            if (s < 7) ldfrag(s + 1 < 4 ? buf0 : buf1, (s + 1) & 3, (s + 1) & 1);
            if (s == 3) {                         // mid-window: issue 2nd load
                if (i + 3 < NC) load_chunk(i + 3, (i + 3) & 3);
                CP_COMMIT();
            }
            domma(s & 1);
        }
    }

    // ---- epilogue: direct float2 stores + bias ----
    const int gr = lane >> 2;
    const int gc = (lane & 3) * 2;
#pragma unroll
    for (int ni = 0; ni < 8; ni++) {
        const int col = n0 + wn * 64 + ni * 8 + gc;
        const float2 bv = *(const float2*)(bias + col);
#pragma unroll
        for (int mi = 0; mi < 4; mi++) {
            const int row = m0 + wm * 64 + mi * 16 + gr;
            float2 v0 = make_float2(acc[mi][ni][0] + bv.x, acc[mi][ni][1] + bv.y);
            float2 v1 = make_float2(acc[mi][ni][2] + bv.x, acc[mi][ni][3] + bv.y);
            *(float2*)(out + (size_t)row * N + col)       = v0;
            *(float2*)(out + (size_t)(row + 8) * N + col) = v1;
        }
    }
}

// ------------------------------ launcher -------------------------------------
extern "C" void kernel_launch(void* const* d_in, const int* in_sizes, int n_in,
                              void* d_out, int out_size) {
    const float* x    = (const float*)d_in[0];   // [B,T,C] f32
    const float* W    = (const float*)d_in[1];   // [O,C]   f32
    const float* bias = (const float*)d_in[2];   // [O]     f32
    float* out = (float*)d_out;                  // [B,T,O] f32

    const int O = in_sizes[2];
    const int C = in_sizes[1] / O;
    const int M = in_sizes[0] / C;

    void *pxq = nullptr, *pwq = nullptr;
    cudaGetSymbolAddress(&pxq, g_Xq);
    cudaGetSymbolAddress(&pwq, g_Wq);

    const int n4x = in_sizes[0] / 4;
    const int n4w = in_sizes[1] / 4;
    const int n4  = n4x + n4w;
    quant_fp8_fused_kernel<<<(n4 + 255) / 256, 256>>>(
        x, W, (uint32_t*)pxq, (uint32_t*)pwq, n4x, n4w);

    cudaFuncSetAttribute(fp8_gemm_kernel,
                         cudaFuncAttributeMaxDynamicSharedMemorySize, SMEM_TOTAL);
    const int blocks = (M / BM) * (O / BN);
    fp8_gemm_kernel<<<blocks, 256, SMEM_TOTAL>>>(bias, out, M, O, C);
}

// round 8
// speedup vs baseline: 1.0232x; 1.0232x over previous
#include <cuda_runtime.h>
#include <cuda_bf16.h>
#include <cuda_fp8.h>
#include <cstdint>

// Problem shape (fixed by the dataset): M=8192 (B*T), K=4096 (C), N=16384 (O)
#define MAX_M 8192
#define MAX_K 4096
#define MAX_N 16384

// FP8 scratch (device globals: no allocation allowed in kernel_launch)
__device__ __align__(128) uint8_t g_Xq[(size_t)MAX_M * MAX_K];  // 32 MB
__device__ __align__(128) uint8_t g_Wq[(size_t)MAX_N * MAX_K];  // 64 MB

// ----------------------------- helpers -------------------------------------
__device__ __forceinline__ uint32_t smem_u32(const void* p) {
    uint32_t a;
    asm("{ .reg .u64 t; cvta.to.shared.u64 t, %1; cvt.u32.u64 %0, t; }"
        : "=r"(a) : "l"(p));
    return a;
}

#define CP_ASYNC16(saddr, gptr) \
    asm volatile("cp.async.cg.shared.global [%0], [%1], 16;" :: "r"(saddr), "l"(gptr))
#define CP_COMMIT() asm volatile("cp.async.commit_group;" ::: "memory")
#define CP_WAIT(n)  asm volatile("cp.async.wait_group %0;" :: "n"(n) : "memory")

__device__ __forceinline__ void ldsm_x4(uint32_t* r, uint32_t addr) {
    asm volatile("ldmatrix.sync.aligned.m8n8.x4.shared.b16 {%0,%1,%2,%3}, [%4];"
                 : "=r"(r[0]), "=r"(r[1]), "=r"(r[2]), "=r"(r[3]) : "r"(addr));
}

// FP8 e4m3 x e4m3 -> f32 MMA (sm_89+, family-portable)
__device__ __forceinline__ void mma_f8(float* c, const uint32_t* a, const uint32_t* b) {
    asm volatile(
        "mma.sync.aligned.m16n8k32.row.col.f32.e4m3.e4m3.f32 "
        "{%0,%1,%2,%3}, {%4,%5,%6,%7}, {%8,%9}, {%0,%1,%2,%3};"
        : "+f"(c[0]), "+f"(c[1]), "+f"(c[2]), "+f"(c[3])
        : "r"(a[0]), "r"(a[1]), "r"(a[2]), "r"(a[3]), "r"(b[0]), "r"(b[1]));
}

// ------------------------------ constants -----------------------------------
// 2 CTAs/SM: CTA tile 128x128, 4 warps (2M x 2N), warp tile 64x64.
// 128 thr x 2 CTA = 256 thr/SM -> 256 regs/thread available to BOTH CTAs.
#define BM 128
#define BN 128
#define BK 128
#define STAGES 3
#define STAGE_A (BM * BK)                       // 16384
#define STAGE_B (BN * BK)                       // 16384
#define STAGE_BYTES (STAGE_A + STAGE_B)         // 32768
#define SMEM_TOTAL (STAGES * STAGE_BYTES)       // 98304 (x2 CTA = 196608/SM)

// ------------------------------ quantize ------------------------------------
// Fused single launch (keeps ncu's -s 5 -c 1 window on the GEMM).
// satfinite e4m3 == clamp(-448,448) + round-to-nearest-even -> matches reference
__device__ __forceinline__ uint32_t q4(const float4 v) {
    __nv_fp8x2_storage_t lo =
        __nv_cvt_float2_to_fp8x2(make_float2(v.x, v.y), __NV_SATFINITE, __NV_E4M3);
    __nv_fp8x2_storage_t hi =
        __nv_cvt_float2_to_fp8x2(make_float2(v.z, v.w), __NV_SATFINITE, __NV_E4M3);
    return (uint32_t)lo | ((uint32_t)hi << 16);
}

__global__ void quant_fp8_fused_kernel(const float* __restrict__ x,
                                       const float* __restrict__ w,
                                       uint32_t* __restrict__ xq,
                                       uint32_t* __restrict__ wq,
                                       int n4x, int n4w) {
    int i = blockIdx.x * blockDim.x + threadIdx.x;
    if (i < n4x) {
        xq[i] = q4(((const float4*)x)[i]);
    } else {
        int j = i - n4x;
        if (j < n4w) wq[j] = q4(((const float4*)w)[j]);
    }
}

// ------------------------------- GEMM ----------------------------------------
__global__ void __launch_bounds__(128, 2)
fp8_gemm_kernel(const float* __restrict__ bias, float* __restrict__ out,
                int M, int N, int K) {
    extern __shared__ char smem[];
    const uint32_t sbase = smem_u32(smem);
    const int tid  = threadIdx.x;
    const int wid  = tid >> 5;
    const int lane = tid & 31;
    const int wm = wid & 1;    // 2 M-warps x 64 rows
    const int wn = wid >> 1;   // 2 N-warps x 64 cols

    // ---- grouped rasterization for L2 reuse ----
    const int tiles_m = M / BM;   // 64
    const int tiles_n = N / BN;   // 128
    const int GRP = 16;
    int bid = blockIdx.x;
    int tpg = GRP * tiles_n;
    int g = bid / tpg, r = bid % tpg;
    int mf = g * GRP;
    int gs = tiles_m - mf; if (gs > GRP) gs = GRP;
    const int m0 = (mf + (r % gs)) * BM;
    const int n0 = (r / gs) * BN;

    const uint8_t* Ag = g_Xq + (size_t)m0 * K;
    const uint8_t* Bg = g_Wq + (size_t)n0 * K;

    // loader: per chunk 2048 x 16B units (A 1024 + B 1024); 16 per thread.
    // rows are 128B; swizzle unit column: cu = c ^ (row & 7) -> conflict-free
    // for both cp.async stores and ldmatrix reads.
    auto load_chunk = [&](int ck, int buf) {
        const uint32_t st = sbase + buf * STAGE_BYTES;
#pragma unroll
        for (int j = 0; j < 16; j++) {
            int u = tid + 128 * j;
            if (u < 1024) {
                int row = u >> 3, c = u & 7;
                CP_ASYNC16(st + row * 128 + ((c ^ (row & 7)) << 4),
                           Ag + (size_t)row * K + ck * BK + c * 16);
            } else {
                int v = u - 1024;
                int row = v >> 3, c = v & 7;
                CP_ASYNC16(st + STAGE_A + row * 128 + ((c ^ (row & 7)) << 4),
                           Bg + (size_t)row * K + ck * BK + c * 16);
            }
        }
    };

    float acc[4][8][4];
#pragma unroll
    for (int mi = 0; mi < 4; mi++)
#pragma unroll
        for (int ni = 0; ni < 8; ni++)
#pragma unroll
            for (int q = 0; q < 4; q++) acc[mi][ni][q] = 0.f;

    const int NC = K / BK;   // 32

    // lane-derived ldmatrix address components (mapping verified rel_err=0)
    const int lr   = lane & 7;
    const int lsel = lane >> 3;                 // 0..3
    const int a_row_off = lr + (lsel & 1) * 8;  // A: bit0 -> +8 rows
    const int a_ku      = lsel >> 1;            //    bit1 -> k-unit
    const int b_ni_off  = lsel >> 1;            // B: bit1 -> n8 within pair
    const int b_ku      = lsel & 1;             //    bit0 -> k-unit

    // consume one K-chunk resident in buffer `buf` (round-6 body, verified)
    auto consume_chunk = [&](int buf) {
        const uint32_t sA = sbase + buf * STAGE_BYTES;
        const uint32_t sB = sA + STAGE_A;
#pragma unroll
        for (int ks = 0; ks < 4; ks++) {       // four k32 steps per 128B chunk
            uint32_t afr[4][4];
#pragma unroll
            for (int mi = 0; mi < 4; mi++) {
                int row  = wm * 64 + mi * 16 + a_row_off;
                int unit = ks * 2 + a_ku;
                int cu   = unit ^ (row & 7);
                ldsm_x4(afr[mi], sA + row * 128 + cu * 16);
            }
            uint32_t bfr[8][2];
#pragma unroll
            for (int nj = 0; nj < 4; nj++) {   // each x4 covers two n8 tiles
                int nrow = wn * 64 + (nj * 2 + b_ni_off) * 8 + lr;
                int unit = ks * 2 + b_ku;
                int cu   = unit ^ (nrow & 7);
                uint32_t t[4];
                ldsm_x4(t, sB + nrow * 128 + cu * 16);
                bfr[nj * 2 + 0][0] = t[0]; bfr[nj * 2 + 0][1] = t[1];
                bfr[nj * 2 + 1][0] = t[2]; bfr[nj * 2 + 1][1] = t[3];
            }
#pragma unroll
            for (int mi = 0; mi < 4; mi++)
#pragma unroll
                for (int ni = 0; ni < 8; ni++)
                    mma_f8(acc[mi][ni], afr[mi], bfr[ni]);
        }
    };

    // ---- 3-stage pipeline, one chunk per barrier ----
    load_chunk(0, 0); CP_COMMIT();
    load_chunk(1, 1); CP_COMMIT();

    for (int i = 0; i < NC; i++) {
        CP_WAIT(1);          // chunk i resident
        __syncthreads();     // buf (i+2)%3 free (consumed at i-1); data visible
        if (i + 2 < NC) load_chunk(i + 2, (i + 2) % 3);
        CP_COMMIT();
        consume_chunk(i % 3);
    }

    // ---- epilogue: direct float2 stores + bias ----
    const int gr = lane >> 2;
    const int gc = (lane & 3) * 2;
#pragma unroll
    for (int ni = 0; ni < 8; ni++) {
        const int col = n0 + wn * 64 + ni * 8 + gc;
        const float2 bv = *(const float2*)(bias + col);
#pragma unroll
        for (int mi = 0; mi < 4; mi++) {
            const int row = m0 + wm * 64 + mi * 16 + gr;
            float2 v0 = make_float2(acc[mi][ni][0] + bv.x, acc[mi][ni][1] + bv.y);
            float2 v1 = make_float2(acc[mi][ni][2] + bv.x, acc[mi][ni][3] + bv.y);
            *(float2*)(out + (size_t)row * N + col)       = v0;
            *(float2*)(out + (size_t)(row + 8) * N + col) = v1;
        }
    }
}

// ------------------------------ launcher -------------------------------------
extern "C" void kernel_launch(void* const* d_in, const int* in_sizes, int n_in,
                              void* d_out, int out_size) {
    const float* x    = (const float*)d_in[0];   // [B,T,C] f32
    const float* W    = (const float*)d_in[1];   // [O,C]   f32
    const float* bias = (const float*)d_in[2];   // [O]     f32
    float* out = (float*)d_out;                  // [B,T,O] f32

    const int O = in_sizes[2];
    const int C = in_sizes[1] / O;
    const int M = in_sizes[0] / C;

    void *pxq = nullptr, *pwq = nullptr;
    cudaGetSymbolAddress(&pxq, g_Xq);
    cudaGetSymbolAddress(&pwq, g_Wq);

    const int n4x = in_sizes[0] / 4;
    const int n4w = in_sizes[1] / 4;
    const int n4  = n4x + n4w;
    quant_fp8_fused_kernel<<<(n4 + 255) / 256, 256>>>(
        x, W, (uint32_t*)pxq, (uint32_t*)pwq, n4x, n4w);

    cudaFuncSetAttribute(fp8_gemm_kernel,
                         cudaFuncAttributeMaxDynamicSharedMemorySize, SMEM_TOTAL);
    const int blocks = (M / BM) * (O / BN);
    fp8_gemm_kernel<<<blocks, 128, SMEM_TOTAL>>>(bias, out, M, O, C);
}

// round 9
// speedup vs baseline: 1.2470x; 1.2186x over previous
#include <cuda_runtime.h>
#include <cuda_bf16.h>
#include <cuda_fp8.h>
#include <cstdint>

// Problem shape (fixed by the dataset): M=8192 (B*T), K=4096 (C), N=16384 (O)
#define MAX_M 8192
#define MAX_K 4096
#define MAX_N 16384

// bf16 scratch holding fp8-quantized values (e4m3 -> bf16 is exact)
__device__ __align__(128) __nv_bfloat16 g_Xb[(size_t)MAX_M * MAX_K];  //  64 MB
__device__ __align__(128) __nv_bfloat16 g_Wb[(size_t)MAX_N * MAX_K];  // 128 MB

// ----------------------------- helpers -------------------------------------
__device__ __forceinline__ uint32_t smem_u32(const void* p) {
    uint32_t a;
    asm("{ .reg .u64 t; cvta.to.shared.u64 t, %1; cvt.u32.u64 %0, t; }"
        : "=r"(a) : "l"(p));
    return a;
}

#define CP_ASYNC16(saddr, gptr) \
    asm volatile("cp.async.cg.shared.global [%0], [%1], 16;" :: "r"(saddr), "l"(gptr))
#define CP_COMMIT() asm volatile("cp.async.commit_group;" ::: "memory")
#define CP_WAIT(n)  asm volatile("cp.async.wait_group %0;" :: "n"(n) : "memory")

__device__ __forceinline__ void ldsm_x4(uint32_t* r, uint32_t addr) {
    asm volatile("ldmatrix.sync.aligned.m8n8.x4.shared.b16 {%0,%1,%2,%3}, [%4];"
                 : "=r"(r[0]), "=r"(r[1]), "=r"(r[2]), "=r"(r[3]) : "r"(addr));
}

// bf16 x bf16 -> f32 MMA (sm_80+). Fragment geometry (32B k-rows) is
// byte-identical to the fp8 m16n8k32 layout used in previous rounds.
__device__ __forceinline__ void mma_bf16(float* c, const uint32_t* a, const uint32_t* b) {
    asm volatile(
        "mma.sync.aligned.m16n8k16.row.col.f32.bf16.bf16.f32 "
        "{%0,%1,%2,%3}, {%4,%5,%6,%7}, {%8,%9}, {%0,%1,%2,%3};"
        : "+f"(c[0]), "+f"(c[1]), "+f"(c[2]), "+f"(c[3])
        : "r"(a[0]), "r"(a[1]), "r"(a[2]), "r"(a[3]), "r"(b[0]), "r"(b[1]));
}

// ------------------------------ constants -----------------------------------
// CTA tile 256x128, 8 warps (4M x 2N), warp tile 64x64  (round-6 best config).
// K-chunk = 128 BYTES per row = 64 bf16 elements.
#define BM 256
#define BN 128
#define BKB 128                                 // chunk K-bytes per row
#define BKE 64                                  // chunk K-elements
#define STAGES 4
#define STAGE_A (BM * BKB)                      // 32768
#define STAGE_B (BN * BKB)                      // 16384
#define STAGE_BYTES (STAGE_A + STAGE_B)         // 49152
#define SMEM_TOTAL (STAGES * STAGE_BYTES)       // 196608

// ------------------------------ quantize ------------------------------------
// x -> clamp/round to e4m3 (satfinite) -> bf16 (exact). Matches reference
// fp8 quantize->dequantize semantics bit-for-bit.
__device__ __forceinline__ uint32_t q2bf(float a, float b) {
    __nv_fp8x2_storage_t p8 =
        __nv_cvt_float2_to_fp8x2(make_float2(a, b), __NV_SATFINITE, __NV_E4M3);
    __half2_raw hr = __nv_cvt_fp8x2_to_halfraw2(p8, __NV_E4M3);   // exact
    __half2 h = *reinterpret_cast<__half2*>(&hr);
    float2 f = __half22float2(h);                                  // exact
    __nv_bfloat162 bb = __float22bfloat162_rn(f);                  // exact (e4m3)
    return *reinterpret_cast<uint32_t*>(&bb);
}

__global__ void quant_fused_kernel(const float* __restrict__ x,
                                   const float* __restrict__ w,
                                   uint2* __restrict__ xb,
                                   uint2* __restrict__ wb,
                                   int n4x, int n4w) {
    int i = blockIdx.x * blockDim.x + threadIdx.x;
    if (i < n4x) {
        float4 v = ((const float4*)x)[i];
        xb[i] = make_uint2(q2bf(v.x, v.y), q2bf(v.z, v.w));
    } else {
        int j = i - n4x;
        if (j < n4w) {
            float4 v = ((const float4*)w)[j];
            wb[j] = make_uint2(q2bf(v.x, v.y), q2bf(v.z, v.w));
        }
    }
}

// ------------------------------- GEMM ----------------------------------------
__global__ void __launch_bounds__(256, 1)
fp8_gemm_kernel(const float* __restrict__ bias, float* __restrict__ out,
                int M, int N, int K) {
    extern __shared__ char smem[];
    const uint32_t sbase = smem_u32(smem);
    const int tid  = threadIdx.x;
    const int wid  = tid >> 5;
    const int lane = tid & 31;
    const int wm = wid & 3;    // 4 M-warps x 64 rows
    const int wn = wid >> 2;   // 2 N-warps x 64 cols

    // ---- grouped rasterization for L2 reuse ----
    const int tiles_m = M / BM;   // 32
    const int tiles_n = N / BN;   // 128
    const int GRP = 8;
    int bid = blockIdx.x;
    int tpg = GRP * tiles_n;
    int g = bid / tpg, r = bid % tpg;
    int mf = g * GRP;
    int gs = tiles_m - mf; if (gs > GRP) gs = GRP;
    const int m0 = (mf + (r % gs)) * BM;
    const int n0 = (r / gs) * BN;

    const uint8_t* Ag = (const uint8_t*)g_Xb + (size_t)m0 * K * 2;
    const uint8_t* Bg = (const uint8_t*)g_Wb + (size_t)n0 * K * 2;
    const size_t rowbytes = (size_t)K * 2;

    // loader: per chunk 3072 x 16B units (A 2048 + B 1024); 12 per thread.
    // rows are 128B in smem; swizzle: cu = c ^ (row & 7) -> conflict-free.
    auto load_chunk = [&](int ck, int buf) {
        const uint32_t st = sbase + buf * STAGE_BYTES;
#pragma unroll
        for (int j = 0; j < 12; j++) {
            int u = tid + 256 * j;
            if (u < 2048) {
                int row = u >> 3, c = u & 7;
                CP_ASYNC16(st + row * 128 + ((c ^ (row & 7)) << 4),
                           Ag + (size_t)row * rowbytes + ck * BKB + c * 16);
            } else {
                int v = u - 2048;
                int row = v >> 3, c = v & 7;
                CP_ASYNC16(st + STAGE_A + row * 128 + ((c ^ (row & 7)) << 4),
                           Bg + (size_t)row * rowbytes + ck * BKB + c * 16);
            }
        }
    };

    float acc[4][8][4];
#pragma unroll
    for (int mi = 0; mi < 4; mi++)
#pragma unroll
        for (int ni = 0; ni < 8; ni++)
#pragma unroll
            for (int q = 0; q < 4; q++) acc[mi][ni][q] = 0.f;

    const int NC = (K * 2) / BKB;   // 64 chunks of 64 bf16

    // lane-derived ldmatrix address components — identical to the verified
    // fp8 mapping (fragments have the same 32-byte k-row geometry).
    const int lr   = lane & 7;
    const int lsel = lane >> 3;                 // 0..3
    const int a_row_off = lr + (lsel & 1) * 8;  // A: bit0 -> +8 rows
    const int a_ku      = lsel >> 1;            //    bit1 -> k-unit
    const int b_ni_off  = lsel >> 1;            // B: bit1 -> n8 within pair
    const int b_ku      = lsel & 1;             //    bit0 -> k-unit

    // consume one K-chunk (64 bf16) resident in buffer `buf`
    auto consume_chunk = [&](int buf) {
        const uint32_t sA = sbase + buf * STAGE_BYTES;
        const uint32_t sB = sA + STAGE_A;
#pragma unroll
        for (int ks = 0; ks < 4; ks++) {       // four k16 steps per 128B chunk
            uint32_t afr[4][4];
#pragma unroll
            for (int mi = 0; mi < 4; mi++) {
                int row  = wm * 64 + mi * 16 + a_row_off;
                int unit = ks * 2 + a_ku;
                int cu   = unit ^ (row & 7);
                ldsm_x4(afr[mi], sA + row * 128 + cu * 16);
            }
            uint32_t bfr[8][2];
#pragma unroll
            for (int nj = 0; nj < 4; nj++) {   // each x4 covers two n8 tiles
                int nrow = wn * 64 + (nj * 2 + b_ni_off) * 8 + lr;
                int unit = ks * 2 + b_ku;
                int cu   = unit ^ (nrow & 7);
                uint32_t t[4];
                ldsm_x4(t, sB + nrow * 128 + cu * 16);
                bfr[nj * 2 + 0][0] = t[0]; bfr[nj * 2 + 0][1] = t[1];
                bfr[nj * 2 + 1][0] = t[2]; bfr[nj * 2 + 1][1] = t[3];
            }
#pragma unroll
            for (int mi = 0; mi < 4; mi++)
#pragma unroll
                for (int ni = 0; ni < 8; ni++)
                    mma_bf16(acc[mi][ni], afr[mi], bfr[ni]);
        }
    };

    // ---- pipeline: 2 chunks per barrier, issued one full iteration ahead ----
    load_chunk(0, 0); CP_COMMIT();
    load_chunk(1, 1); CP_COMMIT();

    for (int i = 0; i < NC; i += 2) {
        CP_WAIT(0);          // chunks i, i+1 resident (issued 1 iteration ago)
        __syncthreads();     // bufs (i+2)%4,(i+3)%4 free; data visible
        if (i + 2 < NC) load_chunk(i + 2, (i + 2) & 3);
        CP_COMMIT();
        consume_chunk(i & 3);
        if (i + 3 < NC) load_chunk(i + 3, (i + 3) & 3);
        CP_COMMIT();
        consume_chunk((i + 1) & 3);
    }

    // ---- epilogue: direct float2 stores + bias ----
    const int gr = lane >> 2;
    const int gc = (lane & 3) * 2;
#pragma unroll
    for (int ni = 0; ni < 8; ni++) {
        const int col = n0 + wn * 64 + ni * 8 + gc;
        const float2 bv = *(const float2*)(bias + col);
#pragma unroll
        for (int mi = 0; mi < 4; mi++) {
            const int row = m0 + wm * 64 + mi * 16 + gr;
            float2 v0 = make_float2(acc[mi][ni][0] + bv.x, acc[mi][ni][1] + bv.y);
            float2 v1 = make_float2(acc[mi][ni][2] + bv.x, acc[mi][ni][3] + bv.y);
            *(float2*)(out + (size_t)row * N + col)       = v0;
            *(float2*)(out + (size_t)(row + 8) * N + col) = v1;
        }
    }
}

// ------------------------------ launcher -------------------------------------
extern "C" void kernel_launch(void* const* d_in, const int* in_sizes, int n_in,
                              void* d_out, int out_size) {
    const float* x    = (const float*)d_in[0];   // [B,T,C] f32
    const float* W    = (const float*)d_in[1];   // [O,C]   f32
    const float* bias = (const float*)d_in[2];   // [O]     f32
    float* out = (float*)d_out;                  // [B,T,O] f32

    const int O = in_sizes[2];
    const int C = in_sizes[1] / O;
    const int M = in_sizes[0] / C;

    void *pxb = nullptr, *pwb = nullptr;
    cudaGetSymbolAddress(&pxb, g_Xb);
    cudaGetSymbolAddress(&pwb, g_Wb);

    const int n4x = in_sizes[0] / 4;
    const int n4w = in_sizes[1] / 4;
    const int n4  = n4x + n4w;
    quant_fused_kernel<<<(n4 + 255) / 256, 256>>>(
        x, W, (uint2*)pxb, (uint2*)pwb, n4x, n4w);

    cudaFuncSetAttribute(fp8_gemm_kernel,
                         cudaFuncAttributeMaxDynamicSharedMemorySize, SMEM_TOTAL);
    const int blocks = (M / BM) * (O / BN);
    fp8_gemm_kernel<<<blocks, 256, SMEM_TOTAL>>>(bias, out, M, O, C);
}

// round 10
// speedup vs baseline: 1.3285x; 1.0654x over previous
#include <cuda_runtime.h>
#include <cuda_bf16.h>
#include <cuda_fp8.h>
#include <cstdint>

// Problem shape (fixed by the dataset): M=8192 (B*T), K=4096 (C), N=16384 (O)
#define MAX_M 8192
#define MAX_K 4096
#define MAX_N 16384

// bf16 scratch holding fp8-quantized values (e4m3 -> bf16 is exact)
__device__ __align__(128) __nv_bfloat16 g_Xb[(size_t)MAX_M * MAX_K];  //  64 MB
__device__ __align__(128) __nv_bfloat16 g_Wb[(size_t)MAX_N * MAX_K];  // 128 MB

// ----------------------------- helpers -------------------------------------
__device__ __forceinline__ uint32_t smem_u32(const void* p) {
    uint32_t a;
    asm("{ .reg .u64 t; cvta.to.shared.u64 t, %1; cvt.u32.u64 %0, t; }"
        : "=r"(a) : "l"(p));
    return a;
}

#define CP_ASYNC16(saddr, gptr) \
    asm volatile("cp.async.cg.shared.global [%0], [%1], 16;" :: "r"(saddr), "l"(gptr))
#define CP_COMMIT() asm volatile("cp.async.commit_group;" ::: "memory")
#define CP_WAIT(n)  asm volatile("cp.async.wait_group %0;" :: "n"(n) : "memory")

__device__ __forceinline__ void ldsm_x4(uint32_t* r, uint32_t addr) {
    asm volatile("ldmatrix.sync.aligned.m8n8.x4.shared.b16 {%0,%1,%2,%3}, [%4];"
                 : "=r"(r[0]), "=r"(r[1]), "=r"(r[2]), "=r"(r[3]) : "r"(addr));
}

// bf16 x bf16 -> f32 MMA (sm_80+)
__device__ __forceinline__ void mma_bf16(float* c, const uint32_t* a, const uint32_t* b) {
    asm volatile(
        "mma.sync.aligned.m16n8k16.row.col.f32.bf16.bf16.f32 "
        "{%0,%1,%2,%3}, {%4,%5,%6,%7}, {%8,%9}, {%0,%1,%2,%3};"
        : "+f"(c[0]), "+f"(c[1]), "+f"(c[2]), "+f"(c[3])
        : "r"(a[0]), "r"(a[1]), "r"(a[2]), "r"(a[3]), "r"(b[0]), "r"(b[1]));
}

// ------------------------------ constants -----------------------------------
// CTA tile 256x128, 8 warps (4M x 2N), warp tile 64x64.
// K-chunk = 128 BYTES per row = 64 bf16 elements.
#define BM 256
#define BN 128
#define BKB 128                                 // chunk K-bytes per row
#define STAGES 4
#define STAGE_A (BM * BKB)                      // 32768
#define STAGE_B (BN * BKB)                      // 16384
#define STAGE_BYTES (STAGE_A + STAGE_B)         // 49152
#define SMEM_TOTAL (STAGES * STAGE_BYTES)       // 196608

// ------------------------------ quantize ------------------------------------
// x -> clamp/round to e4m3 (satfinite) -> bf16 (exact). Matches reference
// fp8 quantize->dequantize semantics bit-for-bit.
__device__ __forceinline__ uint32_t q2bf(float a, float b) {
    __nv_fp8x2_storage_t p8 =
        __nv_cvt_float2_to_fp8x2(make_float2(a, b), __NV_SATFINITE, __NV_E4M3);
    __half2_raw hr = __nv_cvt_fp8x2_to_halfraw2(p8, __NV_E4M3);   // exact
    __half2 h = *reinterpret_cast<__half2*>(&hr);
    float2 f = __half22float2(h);                                  // exact
    __nv_bfloat162 bb = __float22bfloat162_rn(f);                  // exact (e4m3)
    return *reinterpret_cast<uint32_t*>(&bb);
}

__global__ void quant_fused_kernel(const float* __restrict__ x,
                                   const float* __restrict__ w,
                                   uint2* __restrict__ xb,
                                   uint2* __restrict__ wb,
                                   int n4x, int n4w) {
    int i = blockIdx.x * blockDim.x + threadIdx.x;
    if (i < n4x) {
        float4 v = ((const float4*)x)[i];
        xb[i] = make_uint2(q2bf(v.x, v.y), q2bf(v.z, v.w));
    } else {
        int j = i - n4x;
        if (j < n4w) {
            float4 v = ((const float4*)w)[j];
            wb[j] = make_uint2(q2bf(v.x, v.y), q2bf(v.z, v.w));
        }
    }
}

// ------------------------------- GEMM ----------------------------------------
__global__ void __launch_bounds__(256, 1)
fp8_gemm_kernel(const float* __restrict__ bias, float* __restrict__ out,
                int M, int N, int K) {
    extern __shared__ char smem[];
    const uint32_t sbase = smem_u32(smem);
    const int tid  = threadIdx.x;
    const int wid  = tid >> 5;
    const int lane = tid & 31;
    const int wm = wid & 3;    // 4 M-warps x 64 rows
    const int wn = wid >> 2;   // 2 N-warps x 64 cols

    // ---- grouped rasterization for L2 reuse ----
    const int tiles_m = M / BM;   // 32
    const int tiles_n = N / BN;   // 128
    const int GRP = 8;
    int bid = blockIdx.x;
    int tpg = GRP * tiles_n;
    int g = bid / tpg, r = bid % tpg;
    int mf = g * GRP;
    int gs = tiles_m - mf; if (gs > GRP) gs = GRP;
    const int m0 = (mf + (r % gs)) * BM;
    const int n0 = (r / gs) * BN;

    const uint8_t* Ag = (const uint8_t*)g_Xb + (size_t)m0 * K * 2;
    const uint8_t* Bg = (const uint8_t*)g_Wb + (size_t)n0 * K * 2;
    const size_t rowbytes = (size_t)K * 2;

    // loader: per chunk 3072 x 16B units (A 2048 + B 1024); 12 per thread.
    // rows are 128B in smem; swizzle: cu = c ^ (row & 7) -> conflict-free.
    auto load_chunk = [&](int ck, int buf) {
        const uint32_t st = sbase + buf * STAGE_BYTES;
#pragma unroll
        for (int j = 0; j < 12; j++) {
            int u = tid + 256 * j;
            if (u < 2048) {
                int row = u >> 3, c = u & 7;
                CP_ASYNC16(st + row * 128 + ((c ^ (row & 7)) << 4),
                           Ag + (size_t)row * rowbytes + ck * BKB + c * 16);
            } else {
                int v = u - 2048;
                int row = v >> 3, c = v & 7;
                CP_ASYNC16(st + STAGE_A + row * 128 + ((c ^ (row & 7)) << 4),
                           Bg + (size_t)row * rowbytes + ck * BKB + c * 16);
            }
        }
    };

    float acc[4][8][4];
#pragma unroll
    for (int mi = 0; mi < 4; mi++)
#pragma unroll
        for (int ni = 0; ni < 8; ni++)
#pragma unroll
            for (int q = 0; q < 4; q++) acc[mi][ni][q] = 0.f;

    const int NC = (K * 2) / BKB;   // 64 chunks of 64 bf16

    // lane-derived ldmatrix address components (mapping verified rel_err=0)
    const int lr   = lane & 7;
    const int lsel = lane >> 3;                 // 0..3
    const int a_row_off = lr + (lsel & 1) * 8;  // A: bit0 -> +8 rows
    const int a_ku      = lsel >> 1;            //    bit1 -> k-unit
    const int b_ni_off  = lsel >> 1;            // B: bit1 -> n8 within pair
    const int b_ku      = lsel & 1;             //    bit0 -> k-unit

    // precomputed byte offsets within a stage (row&7 == lr for all our rows)
    const uint32_t a_base = (uint32_t)(wm * 64 + a_row_off) * 128;
    const uint32_t b_base = STAGE_A + (uint32_t)(wn * 64 + b_ni_off * 8 + lr) * 128;

    // fragments: A double-buffered across ks-steps, B single-buffered halves
    uint32_t afr[2][4][4];
    uint32_t bfr[8][2];

    auto ldA = [&](int buf, int ks, int pb) {
        const uint32_t s = sbase + buf * STAGE_BYTES + a_base
                         + ((((ks << 1) | a_ku) ^ lr) << 4);
#pragma unroll
        for (int mi = 0; mi < 4; mi++)
            ldsm_x4(afr[pb][mi], s + mi * 2048);
    };
    auto ldB0 = [&](int buf, int ks) {
        const uint32_t s = sbase + buf * STAGE_BYTES + b_base
                         + ((((ks << 1) | b_ku) ^ lr) << 4);
        uint32_t t[4];
        ldsm_x4(t, s);
        bfr[0][0] = t[0]; bfr[0][1] = t[1]; bfr[1][0] = t[2]; bfr[1][1] = t[3];
        ldsm_x4(t, s + 2048);
        bfr[2][0] = t[0]; bfr[2][1] = t[1]; bfr[3][0] = t[2]; bfr[3][1] = t[3];
    };
    auto ldB1 = [&](int buf, int ks) {
        const uint32_t s = sbase + buf * STAGE_BYTES + b_base
                         + ((((ks << 1) | b_ku) ^ lr) << 4);
        uint32_t t[4];
        ldsm_x4(t, s + 4096);
        bfr[4][0] = t[0]; bfr[4][1] = t[1]; bfr[5][0] = t[2]; bfr[5][1] = t[3];
        ldsm_x4(t, s + 6144);
        bfr[6][0] = t[0]; bfr[6][1] = t[1]; bfr[7][0] = t[2]; bfr[7][1] = t[3];
    };

    // ---- pipeline: 2-chunk windows; fragments software-pipelined ------------
    load_chunk(0, 0); CP_COMMIT();
    load_chunk(1, 1); CP_COMMIT();

    for (int i = 0; i < NC; i += 2) {
        CP_WAIT(0);          // chunks i, i+1 resident (issued 1 window ago)
        __syncthreads();     // bufs (i+2)%4,(i+3)%4 free; data visible
        const int b0 = i & 3, b1 = (i + 1) & 3;

        // prime step 0 (only exposed LDSM batch in the window)
        ldA(b0, 0, 0); ldB0(b0, 0); ldB1(b0, 0);

#pragma unroll
        for (int s = 0; s < 8; s++) {           // 8 k16-steps over 2 chunks
            const int nb = (s + 1) < 4 ? b0 : b1;
            const int nk = (s + 1) & 3;
            if (s < 7) ldA(nb, nk, (s + 1) & 1);     // A(s+1): 32 MMAs early
#pragma unroll
            for (int mi = 0; mi < 4; mi++)           // half 0: ni 0..3
#pragma unroll
                for (int ni = 0; ni < 4; ni++)
                    mma_bf16(acc[mi][ni], afr[s & 1][mi], bfr[ni]);
            if (s == 1 && i + 2 < NC) { load_chunk(i + 2, (i + 2) & 3); CP_COMMIT(); }
            if (s < 7) ldB0(nb, nk);                 // B0(s+1): 16 MMAs early
#pragma unroll
            for (int mi = 0; mi < 4; mi++)           // half 1: ni 4..7
#pragma unroll
                for (int ni = 4; ni < 8; ni++)
                    mma_bf16(acc[mi][ni], afr[s & 1][mi], bfr[ni]);
            if (s == 3 && i + 3 < NC) { load_chunk(i + 3, (i + 3) & 3); CP_COMMIT(); }
            if (s < 7) ldB1(nb, nk);                 // B1(s+1): 16 MMAs early
        }
    }

    // ---- epilogue: direct float2 stores + bias ----
    const int gr = lane >> 2;
    const int gc = (lane & 3) * 2;
#pragma unroll
    for (int ni = 0; ni < 8; ni++) {
        const int col = n0 + wn * 64 + ni * 8 + gc;
        const float2 bv = *(const float2*)(bias + col);
#pragma unroll
        for (int mi = 0; mi < 4; mi++) {
            const int row = m0 + wm * 64 + mi * 16 + gr;
            float2 v0 = make_float2(acc[mi][ni][0] + bv.x, acc[mi][ni][1] + bv.y);
            float2 v1 = make_float2(acc[mi][ni][2] + bv.x, acc[mi][ni][3] + bv.y);
            *(float2*)(out + (size_t)row * N + col)       = v0;
            *(float2*)(out + (size_t)(row + 8) * N + col) = v1;
        }
    }
}

// ------------------------------ launcher -------------------------------------
extern "C" void kernel_launch(void* const* d_in, const int* in_sizes, int n_in,
                              void* d_out, int out_size) {
    const float* x    = (const float*)d_in[0];   // [B,T,C] f32
    const float* W    = (const float*)d_in[1];   // [O,C]   f32
    const float* bias = (const float*)d_in[2];   // [O]     f32
    float* out = (float*)d_out;                  // [B,T,O] f32

    const int O = in_sizes[2];
    const int C = in_sizes[1] / O;
    const int M = in_sizes[0] / C;

    void *pxb = nullptr, *pwb = nullptr;
    cudaGetSymbolAddress(&pxb, g_Xb);
    cudaGetSymbolAddress(&pwb, g_Wb);

    const int n4x = in_sizes[0] / 4;
    const int n4w = in_sizes[1] / 4;
    const int n4  = n4x + n4w;
    quant_fused_kernel<<<(n4 + 255) / 256, 256>>>(
        x, W, (uint2*)pxb, (uint2*)pwb, n4x, n4w);

    cudaFuncSetAttribute(fp8_gemm_kernel,
                         cudaFuncAttributeMaxDynamicSharedMemorySize, SMEM_TOTAL);
    const int blocks = (M / BM) * (O / BN);
    fp8_gemm_kernel<<<blocks, 256, SMEM_TOTAL>>>(bias, out, M, O, C);
}

// round 11
// speedup vs baseline: 1.3470x; 1.0139x over previous
#include <cuda_runtime.h>
#include <cuda_bf16.h>
#include <cuda_fp8.h>
#include <cstdint>

// Problem shape (fixed by the dataset): M=8192 (B*T), K=4096 (C), N=16384 (O)
#define MAX_M 8192
#define MAX_K 4096
#define MAX_N 16384

// bf16 scratch holding fp8-quantized values (e4m3 -> bf16 is exact)
__device__ __align__(128) __nv_bfloat16 g_Xb[(size_t)MAX_M * MAX_K];  //  64 MB
__device__ __align__(128) __nv_bfloat16 g_Wb[(size_t)MAX_N * MAX_K];  // 128 MB

// ----------------------------- helpers -------------------------------------
__device__ __forceinline__ uint32_t smem_u32(const void* p) {
    uint32_t a;
    asm("{ .reg .u64 t; cvta.to.shared.u64 t, %1; cvt.u32.u64 %0, t; }"
        : "=r"(a) : "l"(p));
    return a;
}

#define CP_ASYNC16(saddr, gptr) \
    asm volatile("cp.async.cg.shared.global [%0], [%1], 16;" :: "r"(saddr), "l"(gptr))
#define CP_COMMIT() asm volatile("cp.async.commit_group;" ::: "memory")
#define CP_WAIT(n)  asm volatile("cp.async.wait_group %0;" :: "n"(n) : "memory")

__device__ __forceinline__ void ldsm_x4(uint32_t* r, uint32_t addr) {
    asm volatile("ldmatrix.sync.aligned.m8n8.x4.shared.b16 {%0,%1,%2,%3}, [%4];"
                 : "=r"(r[0]), "=r"(r[1]), "=r"(r[2]), "=r"(r[3]) : "r"(addr));
}

// bf16 x bf16 -> f32 MMA (sm_80+)
__device__ __forceinline__ void mma_bf16(float* c, const uint32_t* a, const uint32_t* b) {
    asm volatile(
        "mma.sync.aligned.m16n8k16.row.col.f32.bf16.bf16.f32 "
        "{%0,%1,%2,%3}, {%4,%5,%6,%7}, {%8,%9}, {%0,%1,%2,%3};"
        : "+f"(c[0]), "+f"(c[1]), "+f"(c[2]), "+f"(c[3])
        : "r"(a[0]), "r"(a[1]), "r"(a[2]), "r"(a[3]), "r"(b[0]), "r"(b[1]));
}

// ------------------------------ constants -----------------------------------
// CTA tile 256x128, 8 warps (4M x 2N), warp tile 64x64. Persistent CTAs.
#define BM 256
#define BN 128
#define BKB 128                                 // chunk K-bytes per row
#define STAGES 4
#define STAGE_A (BM * BKB)                      // 32768
#define STAGE_B (BN * BKB)                      // 16384
#define STAGE_BYTES (STAGE_A + STAGE_B)         // 49152
#define SMEM_TOTAL (STAGES * STAGE_BYTES)       // 196608
#define GRP 8

// ------------------------------ quantize ------------------------------------
// x -> clamp/round to e4m3 (satfinite) -> bf16 (exact). Matches reference
// fp8 quantize->dequantize semantics bit-for-bit.
__device__ __forceinline__ uint32_t q2bf(float a, float b) {
    __nv_fp8x2_storage_t p8 =
        __nv_cvt_float2_to_fp8x2(make_float2(a, b), __NV_SATFINITE, __NV_E4M3);
    __half2_raw hr = __nv_cvt_fp8x2_to_halfraw2(p8, __NV_E4M3);   // exact
    __half2 h = *reinterpret_cast<__half2*>(&hr);
    float2 f = __half22float2(h);                                  // exact
    __nv_bfloat162 bb = __float22bfloat162_rn(f);                  // exact (e4m3)
    return *reinterpret_cast<uint32_t*>(&bb);
}

__global__ void quant_fused_kernel(const float* __restrict__ x,
                                   const float* __restrict__ w,
                                   uint2* __restrict__ xb,
                                   uint2* __restrict__ wb,
                                   int n4x, int n4w) {
    int i = blockIdx.x * blockDim.x + threadIdx.x;
    if (i < n4x) {
        float4 v = ((const float4*)x)[i];
        xb[i] = make_uint2(q2bf(v.x, v.y), q2bf(v.z, v.w));
    } else {
        int j = i - n4x;
        if (j < n4w) {
            float4 v = ((const float4*)w)[j];
            wb[j] = make_uint2(q2bf(v.x, v.y), q2bf(v.z, v.w));
        }
    }
}

// grouped rasterization: tile id -> (m0, n0)
__device__ __forceinline__ void tile_coords(int t, int tiles_m, int tiles_n,
                                            int& m0, int& n0) {
    int tpg = GRP * tiles_n;
    int g = t / tpg, r = t % tpg;
    int mf = g * GRP;
    int gs = tiles_m - mf; if (gs > GRP) gs = GRP;
    m0 = (mf + (r % gs)) * BM;
    n0 = (r / gs) * BN;
}

// ------------------------------- GEMM ----------------------------------------
__global__ void __launch_bounds__(256, 1)
fp8_gemm_kernel(const float* __restrict__ bias, float* __restrict__ out,
                int M, int N, int K) {
    extern __shared__ char smem[];
    const uint32_t sbase = smem_u32(smem);
    const int tid  = threadIdx.x;
    const int wid  = tid >> 5;
    const int lane = tid & 31;
    const int wm = wid & 3;    // 4 M-warps x 64 rows
    const int wn = wid >> 2;   // 2 N-warps x 64 cols

    const int tiles_m = M / BM;   // 32
    const int tiles_n = N / BN;   // 128
    const int ntiles  = tiles_m * tiles_n;
    const int G = gridDim.x;
    const size_t rowbytes = (size_t)K * 2;
    const int NC = (K * 2) / BKB;   // 64 chunks of 64 bf16

    // ---- load-side cursor (rolls across tile boundaries) ----
    int t_load = blockIdx.x;
    int ck_load = 0;
    const uint8_t *lAg, *lBg;
    {
        int m0l, n0l; tile_coords(t_load, tiles_m, tiles_n, m0l, n0l);
        lAg = (const uint8_t*)g_Xb + (size_t)m0l * rowbytes;
        lBg = (const uint8_t*)g_Wb + (size_t)n0l * rowbytes;
    }

    // one K-chunk: 3072 x 16B units (A 2048 + B 1024); 12 per thread.
    // smem rows 128B; swizzle cu = c ^ (row & 7) -> conflict-free.
    auto issue_load = [&]() {
        if (t_load < ntiles) {
            const uint32_t st = sbase + (ck_load & 3) * STAGE_BYTES;
            const int ck = ck_load;
#pragma unroll
            for (int j = 0; j < 12; j++) {
                int u = tid + 256 * j;
                if (u < 2048) {
                    int row = u >> 3, c = u & 7;
                    CP_ASYNC16(st + row * 128 + ((c ^ (row & 7)) << 4),
                               lAg + (size_t)row * rowbytes + ck * BKB + c * 16);
                } else {
                    int v = u - 2048;
                    int row = v >> 3, c = v & 7;
                    CP_ASYNC16(st + STAGE_A + row * 128 + ((c ^ (row & 7)) << 4),
                               lBg + (size_t)row * rowbytes + ck * BKB + c * 16);
                }
            }
            if (++ck_load == NC) {
                ck_load = 0;
                t_load += G;
                if (t_load < ntiles) {
                    int m0l, n0l; tile_coords(t_load, tiles_m, tiles_n, m0l, n0l);
                    lAg = (const uint8_t*)g_Xb + (size_t)m0l * rowbytes;
                    lBg = (const uint8_t*)g_Wb + (size_t)n0l * rowbytes;
                }
            }
        }
        CP_COMMIT();
    };

    // lane-derived ldmatrix address components (mapping verified rel_err=0)
    const int lr   = lane & 7;
    const int lsel = lane >> 3;                 // 0..3
    const int a_row_off = lr + (lsel & 1) * 8;  // A: bit0 -> +8 rows
    const int a_ku      = lsel >> 1;            //    bit1 -> k-unit
    const int b_ni_off  = lsel >> 1;            // B: bit1 -> n8 within pair
    const int b_ku      = lsel & 1;             //    bit0 -> k-unit
    const uint32_t a_base = (uint32_t)(wm * 64 + a_row_off) * 128;
    const uint32_t b_base = STAGE_A + (uint32_t)(wn * 64 + b_ni_off * 8 + lr) * 128;

    float acc[4][8][4];
    uint32_t afr[2][4][4];
    uint32_t bfr[8][2];

    auto ldA = [&](int buf, int ks, int pb) {
        const uint32_t s = sbase + buf * STAGE_BYTES + a_base
                         + ((((ks << 1) | a_ku) ^ lr) << 4);
#pragma unroll
        for (int mi = 0; mi < 4; mi++)
            ldsm_x4(afr[pb][mi], s + mi * 2048);
    };
    auto ldB0 = [&](int buf, int ks) {
        const uint32_t s = sbase + buf * STAGE_BYTES + b_base
                         + ((((ks << 1) | b_ku) ^ lr) << 4);
        uint32_t t[4];
        ldsm_x4(t, s);
        bfr[0][0] = t[0]; bfr[0][1] = t[1]; bfr[1][0] = t[2]; bfr[1][1] = t[3];
        ldsm_x4(t, s + 2048);
        bfr[2][0] = t[0]; bfr[2][1] = t[1]; bfr[3][0] = t[2]; bfr[3][1] = t[3];
    };
    auto ldB1 = [&](int buf, int ks) {
        const uint32_t s = sbase + buf * STAGE_BYTES + b_base
                         + ((((ks << 1) | b_ku) ^ lr) << 4);
        uint32_t t[4];
        ldsm_x4(t, s + 4096);
        bfr[4][0] = t[0]; bfr[4][1] = t[1]; bfr[5][0] = t[2]; bfr[5][1] = t[3];
        ldsm_x4(t, s + 6144);
        bfr[6][0] = t[0]; bfr[6][1] = t[1]; bfr[7][0] = t[2]; bfr[7][1] = t[3];
    };

    // ---- prologue: 2 chunks in flight ----
    issue_load();
    issue_load();

    // ---- persistent tile loop ----
    for (int t = blockIdx.x; t < ntiles; t += G) {
#pragma unroll
        for (int mi = 0; mi < 4; mi++)
#pragma unroll
            for (int ni = 0; ni < 8; ni++)
#pragma unroll
                for (int q = 0; q < 4; q++) acc[mi][ni][q] = 0.f;

        for (int i = 0; i < NC; i += 2) {
            CP_WAIT(0);          // chunks i, i+1 resident (issued 1 window ago)
            __syncthreads();     // bufs (i+2)&3,(i+3)&3 free; data visible
            const int b0 = i & 3, b1 = (i + 1) & 3;

            // slim prime: only A(0) + B0(0) exposed
            ldA(b0, 0, 0); ldB0(b0, 0);

#pragma unroll
            for (int s = 0; s < 8; s++) {       // 8 k16-steps over 2 chunks
                const int cb = s < 4 ? b0 : b1;
                const int nb = (s + 1) < 4 ? b0 : b1;
                const int nk = (s + 1) & 3;
                // half0, mi=0 first to put tensor work ahead of ldB1
#pragma unroll
                for (int ni = 0; ni < 4; ni++)
                    mma_bf16(acc[0][ni], afr[s & 1][0], bfr[ni]);
                ldB1(cb, s & 3);                 // B1(s): 12 MMAs before use
#pragma unroll
                for (int mi = 1; mi < 4; mi++)
#pragma unroll
                    for (int ni = 0; ni < 4; ni++)
                        mma_bf16(acc[mi][ni], afr[s & 1][mi], bfr[ni]);
                if (s == 1 || s == 3) issue_load();   // keep +2 chunk lookahead
                if (s < 7) { ldA(nb, nk, (s + 1) & 1); ldB0(nb, nk); }
#pragma unroll
                for (int mi = 0; mi < 4; mi++)   // half1: ni 4..7
#pragma unroll
                    for (int ni = 4; ni < 8; ni++)
                        mma_bf16(acc[mi][ni], afr[s & 1][mi], bfr[ni]);
            }
        }

        // ---- epilogue (no smem; overlaps with already-issued next-tile loads)
        int m0, n0; tile_coords(t, tiles_m, tiles_n, m0, n0);
        const int gr = lane >> 2;
        const int gc = (lane & 3) * 2;
#pragma unroll
        for (int ni = 0; ni < 8; ni++) {
            const int col = n0 + wn * 64 + ni * 8 + gc;
            const float2 bv = *(const float2*)(bias + col);
#pragma unroll
            for (int mi = 0; mi < 4; mi++) {
                const int row = m0 + wm * 64 + mi * 16 + gr;
                float2 v0 = make_float2(acc[mi][ni][0] + bv.x, acc[mi][ni][1] + bv.y);
                float2 v1 = make_float2(acc[mi][ni][2] + bv.x, acc[mi][ni][3] + bv.y);
                *(float2*)(out + (size_t)row * N + col)       = v0;
                *(float2*)(out + (size_t)(row + 8) * N + col) = v1;
            }
        }
    }
}

// ------------------------------ launcher -------------------------------------
extern "C" void kernel_launch(void* const* d_in, const int* in_sizes, int n_in,
                              void* d_out, int out_size) {
    const float* x    = (const float*)d_in[0];   // [B,T,C] f32
    const float* W    = (const float*)d_in[1];   // [O,C]   f32
    const float* bias = (const float*)d_in[2];   // [O]     f32
    float* out = (float*)d_out;                  // [B,T,O] f32

    const int O = in_sizes[2];
    const int C = in_sizes[1] / O;
    const int M = in_sizes[0] / C;

    void *pxb = nullptr, *pwb = nullptr;
    cudaGetSymbolAddress(&pxb, g_Xb);
    cudaGetSymbolAddress(&pwb, g_Wb);

    const int n4x = in_sizes[0] / 4;
    const int n4w = in_sizes[1] / 4;
    const int n4  = n4x + n4w;
    quant_fused_kernel<<<(n4 + 255) / 256, 256>>>(
        x, W, (uint2*)pxb, (uint2*)pwb, n4x, n4w);

    cudaFuncSetAttribute(fp8_gemm_kernel,
                         cudaFuncAttributeMaxDynamicSharedMemorySize, SMEM_TOTAL);

    int nsm = 148;
    cudaDeviceGetAttribute(&nsm, cudaDevAttrMultiProcessorCount, 0);
    const int ntiles = (M / BM) * (O / BN);
    const int blocks = nsm < ntiles ? nsm : ntiles;
    fp8_gemm_kernel<<<blocks, 256, SMEM_TOTAL>>>(bias, out, M, O, C);
}

// round 12
// speedup vs baseline: 1.3735x; 1.0197x over previous
#include <cuda_runtime.h>
#include <cuda_bf16.h>
#include <cuda_fp8.h>
#include <cstdint>

// Problem shape (fixed by the dataset): M=8192 (B*T), K=4096 (C), N=16384 (O)
#define MAX_M 8192
#define MAX_K 4096
#define MAX_N 16384

// bf16 scratch holding fp8-quantized values (e4m3 -> bf16 is exact)
__device__ __align__(128) __nv_bfloat16 g_Xb[(size_t)MAX_M * MAX_K];  //  64 MB
__device__ __align__(128) __nv_bfloat16 g_Wb[(size_t)MAX_N * MAX_K];  // 128 MB

// ----------------------------- helpers -------------------------------------
__device__ __forceinline__ uint32_t smem_u32(const void* p) {
    uint32_t a;
    asm("{ .reg .u64 t; cvta.to.shared.u64 t, %1; cvt.u32.u64 %0, t; }"
        : "=r"(a) : "l"(p));
    return a;
}

#define CP_ASYNC16(saddr, gptr) \
    asm volatile("cp.async.cg.shared.global [%0], [%1], 16;" :: "r"(saddr), "l"(gptr))
#define CP_COMMIT() asm volatile("cp.async.commit_group;" ::: "memory")
#define CP_WAIT(n)  asm volatile("cp.async.wait_group %0;" :: "n"(n) : "memory")

__device__ __forceinline__ void ldsm_x4(uint32_t* r, uint32_t addr) {
    asm volatile("ldmatrix.sync.aligned.m8n8.x4.shared.b16 {%0,%1,%2,%3}, [%4];"
                 : "=r"(r[0]), "=r"(r[1]), "=r"(r[2]), "=r"(r[3]) : "r"(addr));
}

// bf16 x bf16 -> f32 MMA (sm_80+)
__device__ __forceinline__ void mma_bf16(float* c, const uint32_t* a, const uint32_t* b) {
    asm volatile(
        "mma.sync.aligned.m16n8k16.row.col.f32.bf16.bf16.f32 "
        "{%0,%1,%2,%3}, {%4,%5,%6,%7}, {%8,%9}, {%0,%1,%2,%3};"
        : "+f"(c[0]), "+f"(c[1]), "+f"(c[2]), "+f"(c[3])
        : "r"(a[0]), "r"(a[1]), "r"(a[2]), "r"(a[3]), "r"(b[0]), "r"(b[1]));
}

// ------------------------------ constants -----------------------------------
// CTA tile 256x128, 8 warps (4M x 2N), warp tile 64x64. Persistent CTAs.
#define BM 256
#define BN 128
#define BKB 128                                 // chunk K-bytes per row
#define STAGES 4
#define STAGE_A (BM * BKB)                      // 32768
#define STAGE_B (BN * BKB)                      // 16384
#define STAGE_BYTES (STAGE_A + STAGE_B)         // 49152
#define SMEM_TOTAL (STAGES * STAGE_BYTES)       // 196608
#define GRP 8

// ------------------------------ quantize ------------------------------------
// x -> clamp/round to e4m3 (satfinite) -> bf16 (exact). Matches reference
// fp8 quantize->dequantize semantics bit-for-bit.
__device__ __forceinline__ uint32_t q2bf(float a, float b) {
    __nv_fp8x2_storage_t p8 =
        __nv_cvt_float2_to_fp8x2(make_float2(a, b), __NV_SATFINITE, __NV_E4M3);
    __half2_raw hr = __nv_cvt_fp8x2_to_halfraw2(p8, __NV_E4M3);   // exact
    __half2 h = *reinterpret_cast<__half2*>(&hr);
    float2 f = __half22float2(h);                                  // exact
    __nv_bfloat162 bb = __float22bfloat162_rn(f);                  // exact (e4m3)
    return *reinterpret_cast<uint32_t*>(&bb);
}

__device__ __forceinline__ void quant_one(int i, const float* __restrict__ x,
                                          const float* __restrict__ w,
                                          uint2* __restrict__ xb,
                                          uint2* __restrict__ wb,
                                          int n4x, int n4w) {
    if (i < n4x) {
        float4 v = ((const float4*)x)[i];
        xb[i] = make_uint2(q2bf(v.x, v.y), q2bf(v.z, v.w));
    } else {
        int j = i - n4x;
        if (j < n4w) {
            float4 v = ((const float4*)w)[j];
            wb[j] = make_uint2(q2bf(v.x, v.y), q2bf(v.z, v.w));
        }
    }
}

// two float4 per thread (better MLP; quant is DRAM-bound)
__global__ void quant_fused_kernel(const float* __restrict__ x,
                                   const float* __restrict__ w,
                                   uint2* __restrict__ xb,
                                   uint2* __restrict__ wb,
                                   int n4x, int n4w, int half) {
    int i = blockIdx.x * blockDim.x + threadIdx.x;
    quant_one(i, x, w, xb, wb, n4x, n4w);
    quant_one(i + half, x, w, xb, wb, n4x, n4w);
}

// grouped rasterization: tile id -> (m0, n0)
__device__ __forceinline__ void tile_coords(int t, int tiles_m, int tiles_n,
                                            int& m0, int& n0) {
    int tpg = GRP * tiles_n;
    int g = t / tpg, r = t % tpg;
    int mf = g * GRP;
    int gs = tiles_m - mf; if (gs > GRP) gs = GRP;
    m0 = (mf + (r % gs)) * BM;
    n0 = (r / gs) * BN;
}

// ------------------------------- GEMM ----------------------------------------
__global__ void __launch_bounds__(256, 1)
fp8_gemm_kernel(const float* __restrict__ bias, float* __restrict__ out,
                int M, int N, int K) {
    extern __shared__ char smem[];
    const uint32_t sbase = smem_u32(smem);
    const int tid  = threadIdx.x;
    const int wid  = tid >> 5;
    const int lane = tid & 31;
    const int wm = wid & 3;    // 4 M-warps x 64 rows
    const int wn = wid >> 2;   // 2 N-warps x 64 cols

    const int tiles_m = M / BM;   // 32
    const int tiles_n = N / BN;   // 128
    const int ntiles  = tiles_m * tiles_n;
    const int G = gridDim.x;
    const size_t rowbytes = (size_t)K * 2;
    const int NC = (K * 2) / BKB;   // 64 chunks of 64 bf16

    // ---- load-side cursor (rolls across tile boundaries) ----
    int t_load = blockIdx.x;
    int ck_load = 0;
    const uint8_t *lAg, *lBg;
    {
        int m0l, n0l; tile_coords(t_load, tiles_m, tiles_n, m0l, n0l);
        lAg = (const uint8_t*)g_Xb + (size_t)m0l * rowbytes;
        lBg = (const uint8_t*)g_Wb + (size_t)n0l * rowbytes;
    }

    // one K-chunk: 3072 x 16B units (A 2048 + B 1024); 12 per thread.
    // smem rows 128B; swizzle cu = c ^ (row & 7) -> conflict-free.
    auto issue_load = [&]() {
        if (t_load < ntiles) {
            const uint32_t st = sbase + (ck_load & 3) * STAGE_BYTES;
            const int ck = ck_load;
#pragma unroll
            for (int j = 0; j < 12; j++) {
                int u = tid + 256 * j;
                if (u < 2048) {
                    int row = u >> 3, c = u & 7;
                    CP_ASYNC16(st + row * 128 + ((c ^ (row & 7)) << 4),
                               lAg + (size_t)row * rowbytes + ck * BKB + c * 16);
                } else {
                    int v = u - 2048;
                    int row = v >> 3, c = v & 7;
                    CP_ASYNC16(st + STAGE_A + row * 128 + ((c ^ (row & 7)) << 4),
                               lBg + (size_t)row * rowbytes + ck * BKB + c * 16);
                }
            }
            if (++ck_load == NC) {
                ck_load = 0;
                t_load += G;
                if (t_load < ntiles) {
                    int m0l, n0l; tile_coords(t_load, tiles_m, tiles_n, m0l, n0l);
                    lAg = (const uint8_t*)g_Xb + (size_t)m0l * rowbytes;
                    lBg = (const uint8_t*)g_Wb + (size_t)n0l * rowbytes;
                }
            }
        }
        CP_COMMIT();
    };

    // lane-derived ldmatrix address components (mapping verified rel_err=0)
    const int lr   = lane & 7;
    const int lsel = lane >> 3;                 // 0..3
    const int a_row_off = lr + (lsel & 1) * 8;  // A: bit0 -> +8 rows
    const int a_ku      = lsel >> 1;            //    bit1 -> k-unit
    const int b_ni_off  = lsel >> 1;            // B: bit1 -> n8 within pair
    const int b_ku      = lsel & 1;             //    bit0 -> k-unit
    const uint32_t a_base = (uint32_t)(wm * 64 + a_row_off) * 128;
    const uint32_t b_base = STAGE_A + (uint32_t)(wn * 64 + b_ni_off * 8 + lr) * 128;

    float acc[4][8][4];
    uint32_t afr[2][4][4];
    uint32_t bfr[8][2];

    auto ldA = [&](int buf, int ks, int pb) {
        const uint32_t s = sbase + buf * STAGE_BYTES + a_base
                         + ((((ks << 1) | a_ku) ^ lr) << 4);
#pragma unroll
        for (int mi = 0; mi < 4; mi++)
            ldsm_x4(afr[pb][mi], s + mi * 2048);
    };
    auto ldB0 = [&](int buf, int ks) {
        const uint32_t s = sbase + buf * STAGE_BYTES + b_base
                         + ((((ks << 1) | b_ku) ^ lr) << 4);
        uint32_t t[4];
        ldsm_x4(t, s);
        bfr[0][0] = t[0]; bfr[0][1] = t[1]; bfr[1][0] = t[2]; bfr[1][1] = t[3];
        ldsm_x4(t, s + 2048);
        bfr[2][0] = t[0]; bfr[2][1] = t[1]; bfr[3][0] = t[2]; bfr[3][1] = t[3];
    };
    auto ldB1 = [&](int buf, int ks) {
        const uint32_t s = sbase + buf * STAGE_BYTES + b_base
                         + ((((ks << 1) | b_ku) ^ lr) << 4);
        uint32_t t[4];
        ldsm_x4(t, s + 4096);
        bfr[4][0] = t[0]; bfr[4][1] = t[1]; bfr[5][0] = t[2]; bfr[5][1] = t[3];
        ldsm_x4(t, s + 6144);
        bfr[6][0] = t[0]; bfr[6][1] = t[1]; bfr[7][0] = t[2]; bfr[7][1] = t[3];
    };

    // ---- prologue: 2 chunks in flight, prime first window ----
    issue_load();
    issue_load();
    CP_WAIT(0);
    __syncthreads();
    ldA(0, 0, 0); ldB0(0, 0);

    // ---- persistent tile loop ----
    for (int t = blockIdx.x; t < ntiles; t += G) {
#pragma unroll
        for (int mi = 0; mi < 4; mi++)
#pragma unroll
            for (int ni = 0; ni < 8; ni++)
#pragma unroll
                for (int q = 0; q < 4; q++) acc[mi][ni][q] = 0.f;

        for (int i = 0; i < NC; i += 2) {
            const int b0 = i & 3, b1 = (i + 1) & 3;
#pragma unroll
            for (int s = 0; s < 8; s++) {       // 8 k16-steps over 2 chunks
                const int cb = s < 4 ? b0 : b1;
                const int nb = (s + 1) < 4 ? b0 : b1;
                const int nk = (s + 1) & 3;
                // half0: mi=0 first so ldB1 sits behind tensor work
#pragma unroll
                for (int ni = 0; ni < 4; ni++)
                    mma_bf16(acc[0][ni], afr[s & 1][0], bfr[ni]);
                ldB1(cb, s & 3);                 // B1(s): 12 MMAs before use
#pragma unroll
                for (int mi = 1; mi < 4; mi++)
#pragma unroll
                    for (int ni = 0; ni < 4; ni++)
                        mma_bf16(acc[mi][ni], afr[s & 1][mi], bfr[ni]);
                if (s == 1 || s == 3) issue_load();   // keep +2 chunk lookahead
                if (s < 7) {
                    ldA(nb, nk, (s + 1) & 1);    // frags(s+1): 16 MMAs early
                    ldB0(nb, nk);
                } else {
                    // window boundary crossed WITH 16 MMAs still in registers:
                    // wait + barrier + prime next window, then issue half1.
                    CP_WAIT(0);                  // chunks i+2, i+3 resident
                    __syncthreads();             // visibility + buffer release
                    ldA((i + 2) & 3, 0, 0);      // prime next window step 0
                    ldB0((i + 2) & 3, 0);        // (safe across tile boundary)
                }
#pragma unroll
                for (int mi = 0; mi < 4; mi++)   // half1: ni 4..7 (regs only)
#pragma unroll
                    for (int ni = 4; ni < 8; ni++)
                        mma_bf16(acc[mi][ni], afr[s & 1][mi], bfr[ni]);
            }
        }

        // ---- epilogue (next window already primed; loads in flight) ----
        int m0, n0; tile_coords(t, tiles_m, tiles_n, m0, n0);
        const int gr = lane >> 2;
        const int gc = (lane & 3) * 2;
#pragma unroll
        for (int ni = 0; ni < 8; ni++) {
            const int col = n0 + wn * 64 + ni * 8 + gc;
            const float2 bv = *(const float2*)(bias + col);
#pragma unroll
            for (int mi = 0; mi < 4; mi++) {
                const int row = m0 + wm * 64 + mi * 16 + gr;
                float2 v0 = make_float2(acc[mi][ni][0] + bv.x, acc[mi][ni][1] + bv.y);
                float2 v1 = make_float2(acc[mi][ni][2] + bv.x, acc[mi][ni][3] + bv.y);
                *(float2*)(out + (size_t)row * N + col)       = v0;
                *(float2*)(out + (size_t)(row + 8) * N + col) = v1;
            }
        }
    }
}

// ------------------------------ launcher -------------------------------------
extern "C" void kernel_launch(void* const* d_in, const int* in_sizes, int n_in,
                              void* d_out, int out_size) {
    const float* x    = (const float*)d_in[0];   // [B,T,C] f32
    const float* W    = (const float*)d_in[1];   // [O,C]   f32
    const float* bias = (const float*)d_in[2];   // [O]     f32
    float* out = (float*)d_out;                  // [B,T,O] f32

    const int O = in_sizes[2];
    const int C = in_sizes[1] / O;
    const int M = in_sizes[0] / C;

    void *pxb = nullptr, *pwb = nullptr;
    cudaGetSymbolAddress(&pxb, g_Xb);
    cudaGetSymbolAddress(&pwb, g_Wb);

    const int n4x = in_sizes[0] / 4;
    const int n4w = in_sizes[1] / 4;
    const int n4  = n4x + n4w;
    const int half = (n4 + 1) / 2;
    quant_fused_kernel<<<(half + 255) / 256, 256>>>(
        x, W, (uint2*)pxb, (uint2*)pwb, n4x, n4w, half);

    cudaFuncSetAttribute(fp8_gemm_kernel,
                         cudaFuncAttributeMaxDynamicSharedMemorySize, SMEM_TOTAL);

    int nsm = 148;
    cudaDeviceGetAttribute(&nsm, cudaDevAttrMultiProcessorCount, 0);
    const int ntiles = (M / BM) * (O / BN);
    const int blocks = nsm < ntiles ? nsm : ntiles;
    fp8_gemm_kernel<<<blocks, 256, SMEM_TOTAL>>>(bias, out, M, O, C);
}

// round 13
// speedup vs baseline: 1.3852x; 1.0085x over previous
#include <cuda_runtime.h>
#include <cuda_bf16.h>
#include <cuda_fp8.h>
#include <cstdint>

// Problem shape (fixed by the dataset): M=8192 (B*T), K=4096 (C), N=16384 (O)
#define MAX_M 8192
#define MAX_K 4096
#define MAX_N 16384

// bf16 scratch holding fp8-quantized values (e4m3 -> bf16 is exact)
__device__ __align__(128) __nv_bfloat16 g_Xb[(size_t)MAX_M * MAX_K];  //  64 MB
__device__ __align__(128) __nv_bfloat16 g_Wb[(size_t)MAX_N * MAX_K];  // 128 MB

// ----------------------------- helpers -------------------------------------
__device__ __forceinline__ uint32_t smem_u32(const void* p) {
    uint32_t a;
    asm("{ .reg .u64 t; cvta.to.shared.u64 t, %1; cvt.u32.u64 %0, t; }"
        : "=r"(a) : "l"(p));
    return a;
}

#define CP_ASYNC16(saddr, gptr) \
    asm volatile("cp.async.cg.shared.global [%0], [%1], 16;" :: "r"(saddr), "l"(gptr))
#define CP_COMMIT() asm volatile("cp.async.commit_group;" ::: "memory")
#define CP_WAIT(n)  asm volatile("cp.async.wait_group %0;" :: "n"(n) : "memory")

__device__ __forceinline__ void ldsm_x4(uint32_t* r, uint32_t addr) {
    asm volatile("ldmatrix.sync.aligned.m8n8.x4.shared.b16 {%0,%1,%2,%3}, [%4];"
                 : "=r"(r[0]), "=r"(r[1]), "=r"(r[2]), "=r"(r[3]) : "r"(addr));
}

// bf16 x bf16 -> f32 MMA (sm_80+)
__device__ __forceinline__ void mma_bf16(float* c, const uint32_t* a, const uint32_t* b) {
    asm volatile(
        "mma.sync.aligned.m16n8k16.row.col.f32.bf16.bf16.f32 "
        "{%0,%1,%2,%3}, {%4,%5,%6,%7}, {%8,%9}, {%0,%1,%2,%3};"
        : "+f"(c[0]), "+f"(c[1]), "+f"(c[2]), "+f"(c[3])
        : "r"(a[0]), "r"(a[1]), "r"(a[2]), "r"(a[3]), "r"(b[0]), "r"(b[1]));
}

// streaming (evict-first) float2 store: out is write-once, keep it out of L2
__device__ __forceinline__ void stg_cs_f2(float* p, float a, float b) {
    asm volatile("st.global.cs.v2.f32 [%0], {%1, %2};"
                 :: "l"(p), "f"(a), "f"(b) : "memory");
}

// ------------------------------ constants -----------------------------------
// CTA tile 256x128, 8 warps (4M x 2N), warp tile 64x64. Persistent CTAs.
#define BM 256
#define BN 128
#define BKB 128                                 // chunk K-bytes per row
#define STAGES 4
#define STAGE_A (BM * BKB)                      // 32768
#define STAGE_B (BN * BKB)                      // 16384
#define STAGE_BYTES (STAGE_A + STAGE_B)         // 49152
#define SMEM_TOTAL (STAGES * STAGE_BYTES)       // 196608
#define GRP 8

// ------------------------------ quantize ------------------------------------
// x -> clamp/round to e4m3 (satfinite) -> bf16 (exact). Matches reference
// fp8 quantize->dequantize semantics bit-for-bit.
__device__ __forceinline__ uint32_t q2bf(float a, float b) {
    __nv_fp8x2_storage_t p8 =
        __nv_cvt_float2_to_fp8x2(make_float2(a, b), __NV_SATFINITE, __NV_E4M3);
    __half2_raw hr = __nv_cvt_fp8x2_to_halfraw2(p8, __NV_E4M3);   // exact
    __half2 h = *reinterpret_cast<__half2*>(&hr);
    float2 f = __half22float2(h);                                  // exact
    __nv_bfloat162 bb = __float22bfloat162_rn(f);                  // exact (e4m3)
    return *reinterpret_cast<uint32_t*>(&bb);
}

// each thread: 2 adjacent float4 reads (32B) -> 1 uint4 write (16B)
__global__ void quant_fused_kernel(const float* __restrict__ x,
                                   const float* __restrict__ w,
                                   uint4* __restrict__ xb,
                                   uint4* __restrict__ wb,
                                   int n8x, int n8w) {
    int i = blockIdx.x * blockDim.x + threadIdx.x;
    if (i < n8x) {
        float4 v0 = ((const float4*)x)[2 * i];
        float4 v1 = ((const float4*)x)[2 * i + 1];
        xb[i] = make_uint4(q2bf(v0.x, v0.y), q2bf(v0.z, v0.w),
                           q2bf(v1.x, v1.y), q2bf(v1.z, v1.w));
    } else {
        int j = i - n8x;
        if (j < n8w) {
            float4 v0 = ((const float4*)w)[2 * j];
            float4 v1 = ((const float4*)w)[2 * j + 1];
            wb[j] = make_uint4(q2bf(v0.x, v0.y), q2bf(v0.z, v0.w),
                               q2bf(v1.x, v1.y), q2bf(v1.z, v1.w));
        }
    }
}

// grouped rasterization: tile id -> (m0, n0)
__device__ __forceinline__ void tile_coords(int t, int tiles_m, int tiles_n,
                                            int& m0, int& n0) {
    int tpg = GRP * tiles_n;
    int g = t / tpg, r = t % tpg;
    int mf = g * GRP;
    int gs = tiles_m - mf; if (gs > GRP) gs = GRP;
    m0 = (mf + (r % gs)) * BM;
    n0 = (r / gs) * BN;
}

// ------------------------------- GEMM ----------------------------------------
__global__ void __launch_bounds__(256, 1)
fp8_gemm_kernel(const float* __restrict__ bias, float* __restrict__ out,
                int M, int N, int K) {
    extern __shared__ char smem[];
    const uint32_t sbase = smem_u32(smem);
    const int tid  = threadIdx.x;
    const int wid  = tid >> 5;
    const int lane = tid & 31;
    const int wm = wid & 3;    // 4 M-warps x 64 rows
    const int wn = wid >> 2;   // 2 N-warps x 64 cols

    const int tiles_m = M / BM;   // 32
    const int tiles_n = N / BN;   // 128
    const int ntiles  = tiles_m * tiles_n;
    const int G = gridDim.x;
    const size_t rowbytes = (size_t)K * 2;
    const int NC = (K * 2) / BKB;   // 64 chunks of 64 bf16

    // ---- load-side cursor (rolls across tile boundaries) ----
    int t_load = blockIdx.x;
    int ck_load = 0;
    const uint8_t *lAg, *lBg;
    {
        int m0l, n0l; tile_coords(t_load, tiles_m, tiles_n, m0l, n0l);
        lAg = (const uint8_t*)g_Xb + (size_t)m0l * rowbytes;
        lBg = (const uint8_t*)g_Wb + (size_t)n0l * rowbytes;
    }

    // one K-chunk: 3072 x 16B units (A 2048 + B 1024); 12 per thread.
    // smem rows 128B; swizzle cu = c ^ (row & 7) -> conflict-free.
    auto issue_load = [&]() {
        if (t_load < ntiles) {
            const uint32_t st = sbase + (ck_load & 3) * STAGE_BYTES;
            const int ck = ck_load;
#pragma unroll
            for (int j = 0; j < 12; j++) {
                int u = tid + 256 * j;
                if (u < 2048) {
                    int row = u >> 3, c = u & 7;
                    CP_ASYNC16(st + row * 128 + ((c ^ (row & 7)) << 4),
                               lAg + (size_t)row * rowbytes + ck * BKB + c * 16);
                } else {
                    int v = u - 2048;
                    int row = v >> 3, c = v & 7;
                    CP_ASYNC16(st + STAGE_A + row * 128 + ((c ^ (row & 7)) << 4),
                               lBg + (size_t)row * rowbytes + ck * BKB + c * 16);
                }
            }
            if (++ck_load == NC) {
                ck_load = 0;
                t_load += G;
                if (t_load < ntiles) {
                    int m0l, n0l; tile_coords(t_load, tiles_m, tiles_n, m0l, n0l);
                    lAg = (const uint8_t*)g_Xb + (size_t)m0l * rowbytes;
                    lBg = (const uint8_t*)g_Wb + (size_t)n0l * rowbytes;
                }
            }
        }
        CP_COMMIT();
    };

    // lane-derived ldmatrix address components (mapping verified rel_err=0)
    const int lr   = lane & 7;
    const int lsel = lane >> 3;                 // 0..3
    const int a_row_off = lr + (lsel & 1) * 8;  // A: bit0 -> +8 rows
    const int a_ku      = lsel >> 1;            //    bit1 -> k-unit
    const int b_ni_off  = lsel >> 1;            // B: bit1 -> n8 within pair
    const int b_ku      = lsel & 1;             //    bit0 -> k-unit
    const uint32_t a_base = (uint32_t)(wm * 64 + a_row_off) * 128;
    const uint32_t b_base = STAGE_A + (uint32_t)(wn * 64 + b_ni_off * 8 + lr) * 128;

    float acc[4][8][4];
    uint32_t afr[2][4][4];
    uint32_t bfr[8][2];

    auto ldA = [&](int buf, int ks, int pb) {
        const uint32_t s = sbase + buf * STAGE_BYTES + a_base
                         + ((((ks << 1) | a_ku) ^ lr) << 4);
#pragma unroll
        for (int mi = 0; mi < 4; mi++)
            ldsm_x4(afr[pb][mi], s + mi * 2048);
    };
    auto ldB0 = [&](int buf, int ks) {
        const uint32_t s = sbase + buf * STAGE_BYTES + b_base
                         + ((((ks << 1) | b_ku) ^ lr) << 4);
        uint32_t t[4];
        ldsm_x4(t, s);
        bfr[0][0] = t[0]; bfr[0][1] = t[1]; bfr[1][0] = t[2]; bfr[1][1] = t[3];
        ldsm_x4(t, s + 2048);
        bfr[2][0] = t[0]; bfr[2][1] = t[1]; bfr[3][0] = t[2]; bfr[3][1] = t[3];
    };
    auto ldB1 = [&](int buf, int ks) {
        const uint32_t s = sbase + buf * STAGE_BYTES + b_base
                         + ((((ks << 1) | b_ku) ^ lr) << 4);
        uint32_t t[4];
        ldsm_x4(t, s + 4096);
        bfr[4][0] = t[0]; bfr[4][1] = t[1]; bfr[5][0] = t[2]; bfr[5][1] = t[3];
        ldsm_x4(t, s + 6144);
        bfr[6][0] = t[0]; bfr[6][1] = t[1]; bfr[7][0] = t[2]; bfr[7][1] = t[3];
    };

    // ---- prologue: 2 chunks in flight, prime first window ----
    issue_load();
    issue_load();
    CP_WAIT(0);
    __syncthreads();
    ldA(0, 0, 0); ldB0(0, 0);

    // ---- persistent tile loop ----
    for (int t = blockIdx.x; t < ntiles; t += G) {
#pragma unroll
        for (int mi = 0; mi < 4; mi++)
#pragma unroll
            for (int ni = 0; ni < 8; ni++)
#pragma unroll
                for (int q = 0; q < 4; q++) acc[mi][ni][q] = 0.f;

        for (int i = 0; i < NC; i += 2) {
            const int b0 = i & 3, b1 = (i + 1) & 3;
#pragma unroll
            for (int s = 0; s < 8; s++) {       // 8 k16-steps over 2 chunks
                const int cb = s < 4 ? b0 : b1;
                const int nb = (s + 1) < 4 ? b0 : b1;
                const int nk = (s + 1) & 3;
                // half0: mi=0 first so ldB1 sits behind tensor work
#pragma unroll
                for (int ni = 0; ni < 4; ni++)
                    mma_bf16(acc[0][ni], afr[s & 1][0], bfr[ni]);
                ldB1(cb, s & 3);                 // B1(s): 12 MMAs before use
#pragma unroll
                for (int mi = 1; mi < 4; mi++)
#pragma unroll
                    for (int ni = 0; ni < 4; ni++)
                        mma_bf16(acc[mi][ni], afr[s & 1][mi], bfr[ni]);
                if (s == 0 || s == 2) issue_load();   // early chunk lookahead
                if (s < 7) {
                    ldA(nb, nk, (s + 1) & 1);    // frags(s+1): 16 MMAs early
                    ldB0(nb, nk);
                } else {
                    // window boundary crossed WITH 16 MMAs still in registers:
                    // wait + barrier + prime next window, then issue half1.
                    CP_WAIT(0);                  // chunks i+2, i+3 resident
                    __syncthreads();             // visibility + buffer release
                    ldA((i + 2) & 3, 0, 0);      // prime next window step 0
                    ldB0((i + 2) & 3, 0);        // (safe across tile boundary)
                }
#pragma unroll
                for (int mi = 0; mi < 4; mi++)   // half1: ni 4..7 (regs only)
#pragma unroll
                    for (int ni = 4; ni < 8; ni++)
                        mma_bf16(acc[mi][ni], afr[s & 1][mi], bfr[ni]);
            }
        }

        // ---- epilogue (next window already primed; loads in flight) ----
        int m0, n0; tile_coords(t, tiles_m, tiles_n, m0, n0);
        const int gr = lane >> 2;
        const int gc = (lane & 3) * 2;
#pragma unroll
        for (int ni = 0; ni < 8; ni++) {
            const int col = n0 + wn * 64 + ni * 8 + gc;
            const float2 bv = *(const float2*)(bias + col);
#pragma unroll
            for (int mi = 0; mi < 4; mi++) {
                const int row = m0 + wm * 64 + mi * 16 + gr;
                stg_cs_f2(out + (size_t)row * N + col,
                          acc[mi][ni][0] + bv.x, acc[mi][ni][1] + bv.y);
                stg_cs_f2(out + (size_t)(row + 8) * N + col,
                          acc[mi][ni][2] + bv.x, acc[mi][ni][3] + bv.y);
            }
        }
    }
}

// ------------------------------ launcher -------------------------------------
extern "C" void kernel_launch(void* const* d_in, const int* in_sizes, int n_in,
                              void* d_out, int out_size) {
    const float* x    = (const float*)d_in[0];   // [B,T,C] f32
    const float* W    = (const float*)d_in[1];   // [O,C]   f32
    const float* bias = (const float*)d_in[2];   // [O]     f32
    float* out = (float*)d_out;                  // [B,T,O] f32

    const int O = in_sizes[2];
    const int C = in_sizes[1] / O;
    const int M = in_sizes[0] / C;

    void *pxb = nullptr, *pwb = nullptr;
    cudaGetSymbolAddress(&pxb, g_Xb);
    cudaGetSymbolAddress(&pwb, g_Wb);

    const int n8x = in_sizes[0] / 8;
    const int n8w = in_sizes[1] / 8;
    const int n8  = n8x + n8w;
    quant_fused_kernel<<<(n8 + 255) / 256, 256>>>(
        x, W, (uint4*)pxb, (uint4*)pwb, n8x, n8w);

    cudaFuncSetAttribute(fp8_gemm_kernel,
                         cudaFuncAttributeMaxDynamicSharedMemorySize, SMEM_TOTAL);

    int nsm = 148;
    cudaDeviceGetAttribute(&nsm, cudaDevAttrMultiProcessorCount, 0);
    const int ntiles = (M / BM) * (O / BN);
    const int blocks = nsm < ntiles ? nsm : ntiles;
    fp8_gemm_kernel<<<blocks, 256, SMEM_TOTAL>>>(bias, out, M, O, C);
}